// round 15
// baseline (speedup 1.0000x reference)
#include <cuda_runtime.h>
#include <cuda_bf16.h>

// ============================================================================
// SNN forward, factorized per-layer across time. Numerics bit-match the
// XLA:CPU (Eigen gebp) reference: per output element, ascending-k fused-FMA
// chain with panel folds at kc=320; scans unfused per-op rounding.
//
// v2 perf: A operand kept as BITS end-to-end (ballot-packed by the scans),
// GEMM uses predicated FFMA2 with a loop-invariant packed amp (exact skip of
// zero terms), 8x8 microtile, C stored [t][n][b] so scans ballot in-place.
// ============================================================================

constexpr int BATCH  = 2048;
constexpr int TSTEPS = 32;
constexpr int F_IN   = 2048;
constexpr int KC     = 320;      // Eigen f32 kc cap

// ---- scratch (static __device__ arrays: no allocations allowed) ------------
__device__ float    g_C [(size_t)TSTEPS * 512 * BATCH];       // 128 MB [t][n][b]
__device__ unsigned g_A1[(size_t)TSTEPS * 64 * F_IN];         // bits [t][wb][k]
__device__ unsigned g_A2[(size_t)TSTEPS * 64 * 512];
__device__ unsigned g_A3[(size_t)TSTEPS * 64 * 512];
__device__ unsigned g_A4[(size_t)TSTEPS * 64 * 256];

// ---- packed f32x2 helpers ---------------------------------------------------
__device__ __forceinline__ unsigned long long pack2(float lo, float hi) {
    unsigned long long r;
    asm("mov.b64 %0, {%1, %2};" : "=l"(r) : "f"(lo), "f"(hi));
    return r;
}
__device__ __forceinline__ float2 unpack2(unsigned long long v) {
    float2 r;
    asm("mov.b64 {%0, %1}, %2;" : "=f"(r.x), "=f"(r.y) : "l"(v));
    return r;
}
__device__ __forceinline__ unsigned long long add2(unsigned long long a,
                                                   unsigned long long b) {
    unsigned long long r;
    asm("add.rn.f32x2 %0, %1, %2;" : "=l"(r) : "l"(a), "l"(b));
    return r;
}
// Predicated packed FMA row: if (bitv) { p_j += amp2 * b_j } for 4 pairs.
// Skipping when bit==0 is bit-exact (fma(+0, b, acc) == acc; acc never -0).
#define MMA_ROW(p0, p1, p2, p3, bitv, amp2, b0, b1, b2, b3)        \
    asm volatile("{\n\t"                                           \
        ".reg .pred q;\n\t"                                        \
        "setp.ne.b32 q, %8, 0;\n\t"                                \
        "@q fma.rn.f32x2 %0, %9, %4, %0;\n\t"                      \
        "@q fma.rn.f32x2 %1, %9, %5, %1;\n\t"                      \
        "@q fma.rn.f32x2 %2, %9, %6, %2;\n\t"                      \
        "@q fma.rn.f32x2 %3, %9, %7, %3;\n\t"                      \
        "}"                                                        \
        : "+l"(p0), "+l"(p1), "+l"(p2), "+l"(p3)                   \
        : "l"(b0), "l"(b1), "l"(b2), "l"(b3), "r"(bitv), "l"(amp2))

// ============================================================================
// Encoder + in-kernel bit transpose: current = (2*fs)*x, 32 LIF steps
// (unfused), ballot over b-lanes -> Abits[t][wb][f].
// ============================================================================
__global__ void encoder_kernel(const float* __restrict__ x,
                               unsigned* __restrict__ A1,
                               const float* __restrict__ fs)
{
    __shared__ float xt[32][33];
    const int tid = threadIdx.x;
    const int bx  = blockIdx.x;
    const int f0  = (bx & 63) * 32;
    const int b0  = (bx >> 6) * 32;
    const int lane = tid & 31;
    const int w    = tid >> 5;

    // coalesced 32x32 tile load (rows = b, cols = f)
#pragma unroll
    for (int rr = w; rr < 32; rr += 8)
        xt[rr][lane] = x[(size_t)(b0 + rr) * F_IN + f0 + lane];
    __syncthreads();

    const float fs2 = __fmul_rn(2.0f, fs[0]);
    const int wb = b0 >> 5;

    for (int c = w; c < 32; c += 8) {           // lane = b, column c = f
        float cur = __fmul_rn(fs2, xt[lane][c]);
        float v = 0.0f;
        unsigned myw = 0u;
#pragma unroll
        for (int t = 0; t < TSTEPS; t++) {
            float t1 = __fadd_rn(cur, -v);
            float t2 = __fmul_rn(0.1f, t1);
            v = __fadd_rn(v, t2);
            bool z = __fadd_rn(v, -0.33f) > 0.0f;
            if (z) v = 0.0f;
            unsigned bal = __ballot_sync(0xffffffffu, z);
            if (lane == t) myw = bal;
        }
        A1[((size_t)lane * 64 + wb) * F_IN + f0 + c] = myw;   // t = lane
    }
}

// ============================================================================
// GEMM over bit-packed A (Eigen accumulation order preserved):
//   C[t][n][b] = chain_k fma(amp*bit, W[n][k], .), folds at kc=320.
// Block: 4 t x 32 b (m=128) x 128 n. Per-thread 8m x 8n. A read as bits
// (1 LDS.32 broadcast per k), B as f32 (2 LDS.128 per k).
// ============================================================================
__global__ __launch_bounds__(256, 1)
void gemm_bits_kernel(const unsigned* __restrict__ Abits,   // [T][64][K]
                      const float*    __restrict__ W,       // [N, K] row-major
                      float*          __restrict__ C,       // [T][N][2048]
                      int K, int N,
                      const float* __restrict__ amp_ptr, float amp_mul)
{
    const int by = blockIdx.y;
    const int t0 = (by >> 6) << 2;      // 8 t-blocks of 4
    const int wb = by & 63;             // b-word (32 b's)
    const int n0 = blockIdx.x * 128;

    float amp = amp_mul;
    if (amp_ptr) amp = __fmul_rn(amp_mul, amp_ptr[0]);
    const unsigned long long AMP2 = pack2(amp, amp);

    __shared__ float    Bs[16][132];    // [k][n]
    __shared__ unsigned sA[4][16];      // [dt][k] bit-words (32 b's each)

    const int tid = threadIdx.x;
    const int tm0 = (tid >> 4) << 3;    // 0..120 (8 m rows, same t)
    const int tn0 = (tid & 15) << 3;    // 0..120 (8 n cols)
    const int dts = tm0 >> 5;           // this thread's dt
    const int sh  = tm0 & 24;           // byte shift within bit-word

    // B loader: row lm (0..127), k-half lk (0/8)
    const int lm = tid >> 1;
    const int lk = (tid & 1) << 3;
    const bool  bvalid = (n0 + lm) < N;
    const float* wbase = W + (size_t)(n0 + (bvalid ? lm : 0)) * K + lk;

    // A loader: threads 0..63 -> (dt = tid>>4, kk = tid&15)
    const bool aload = (tid < 64);
    const unsigned* abase = Abits
        + ((size_t)(t0 + (tid >> 4)) * 64 + wb) * K + (tid & 15);

    // accumulators: panel partial p + running acc, 8m x 4 packed-n pairs
    unsigned long long p[8][4], acc[8][4];
#pragma unroll
    for (int i = 0; i < 8; i++)
#pragma unroll
        for (int j = 0; j < 4; j++) { p[i][j] = 0ull; acc[i][j] = 0ull; }

    // ---- prefetch tile 0 ----
    float4 q0, q1;
    if (bvalid) { q0 = *(const float4*)(wbase); q1 = *(const float4*)(wbase + 4); }
    else        { q0 = make_float4(0,0,0,0);    q1 = make_float4(0,0,0,0); }
    unsigned apf = aload ? abase[0] : 0u;

    int kin = 0;
    for (int k0 = 0; k0 < K; k0 += 16) {
        // ---- stage ----
        if (aload) sA[tid >> 4][tid & 15] = apf;
        Bs[lk + 0][lm] = q0.x;  Bs[lk + 1][lm] = q0.y;
        Bs[lk + 2][lm] = q0.z;  Bs[lk + 3][lm] = q0.w;
        Bs[lk + 4][lm] = q1.x;  Bs[lk + 5][lm] = q1.y;
        Bs[lk + 6][lm] = q1.z;  Bs[lk + 7][lm] = q1.w;
        __syncthreads();

        // ---- prefetch next tile ----
        if (k0 + 16 < K) {
            if (bvalid) {
                q0 = *(const float4*)(wbase + k0 + 16);
                q1 = *(const float4*)(wbase + k0 + 20);
            }
            if (aload) apf = abase[k0 + 16];
        }

        // ---- compute: ascending k; predicated FFMA2 chain into p ----
#pragma unroll
        for (int k = 0; k < 16; k++) {
            unsigned bits = (sA[dts][k] >> sh) & 0xffu;
            ulonglong2 bA = *(const ulonglong2*)&Bs[k][tn0];
            ulonglong2 bB = *(const ulonglong2*)&Bs[k][tn0 + 4];
#pragma unroll
            for (int i = 0; i < 8; i++) {
                MMA_ROW(p[i][0], p[i][1], p[i][2], p[i][3],
                        bits & (1u << i), AMP2, bA.x, bA.y, bB.x, bB.y);
            }
        }

        // ---- Eigen panel boundary: acc += p at kc=320 / end of K ----
        kin += 16;
        if (kin == KC || k0 + 16 >= K) {
#pragma unroll
            for (int i = 0; i < 8; i++)
#pragma unroll
                for (int j = 0; j < 4; j++) {
                    acc[i][j] = add2(acc[i][j], p[i][j]);
                    p[i][j] = 0ull;
                }
            kin = 0;
        }
        __syncthreads();
    }

    // ---- epilogue: C[t][n][b], 8 consecutive b per store pair ----
    const int t  = t0 + (tm0 >> 5);
    const int bb = (wb << 5) + (tm0 & 31);
#pragma unroll
    for (int nn = 0; nn < 8; nn++) {
        int n = n0 + tn0 + nn;
        if (n < N) {
            float vals[8];
#pragma unroll
            for (int i = 0; i < 8; i++) {
                float2 f = unpack2(acc[i][nn >> 1]);
                vals[i] = (nn & 1) ? f.y : f.x;
            }
            float* cp = C + ((size_t)t * N + n) * BATCH + bb;
            *(float4*)cp       = make_float4(vals[0], vals[1], vals[2], vals[3]);
            *(float4*)(cp + 4) = make_float4(vals[4], vals[5], vals[6], vals[7]);
        }
    }
}

// ============================================================================
// LIF scan over t per (b, n), lanes = b: consumes C[t][n][b], ballots spike
// bits directly into the transposed layout Abits[t][wb][n]. Unfused math.
// ============================================================================
__global__ void lif_scan_kernel(const float* __restrict__ C,     // [T][N][2048]
                                unsigned* __restrict__ Aout,     // [T][64][N]
                                int N)
{
    int idx = blockIdx.x * blockDim.x + threadIdx.x;   // n * 2048 + b
    int b = idx & 2047;
    int n = idx >> 11;
    int lane = threadIdx.x & 31;
    int wb = b >> 5;

    const float* p = C + (size_t)n * BATCH + b;
    float v = 0.0f, i = 0.0f;
    unsigned myw = 0u;
#pragma unroll
    for (int t = 0; t < TSTEPS; t++) {
        float c = p[(size_t)t * N * BATCH];
        float t1 = __fadd_rn(i, -v);
        float t2 = __fmul_rn(0.1f, t1);
        float vd = __fadd_rn(v, t2);
        bool z = __fadd_rn(vd, -0.33f) > 0.0f;
        v = z ? 0.0f : vd;
        i = __fadd_rn(__fmul_rn(i, 0.8f), c);
        unsigned bal = __ballot_sync(0xffffffffu, z);
        if (lane == t) myw = bal;
    }
    Aout[((size_t)lane * 64 + wb) * N + n] = myw;      // t = lane
}

// ============================================================================
// LI decoder (unfused): vo = vo + 0.1*(-vo + io) (old io); io = io*0.8 + inp.
// C layout [T][100][2048]; out [B][100].
// ============================================================================
__global__ void decode_kernel(const float* __restrict__ Co,
                              float* __restrict__ out)
{
    int idx = blockIdx.x * blockDim.x + threadIdx.x;   // c * 2048 + b
    int b = idx & 2047;
    int c = idx >> 11;
    const float* p = Co + (size_t)c * BATCH + b;
    float vo = 0.0f, io = 0.0f;
#pragma unroll
    for (int t = 0; t < TSTEPS; t++) {
        float cc = p[(size_t)t * 100 * BATCH];
        float t1 = __fadd_rn(io, -vo);
        float t2 = __fmul_rn(0.1f, t1);
        vo = __fadd_rn(vo, t2);
        io = __fadd_rn(__fmul_rn(io, 0.8f), cc);
    }
    out[(size_t)b * 100 + c] = vo;
}

// ============================================================================
// Launch sequence (graph-capturable: kernel launches only, no sync/alloc)
// ============================================================================
extern "C" void kernel_launch(void* const* d_in, const int* in_sizes, int n_in,
                              void* d_out, int out_size)
{
    const float* x     = (const float*)d_in[0];
    const float* w1    = (const float*)d_in[1];   // [512, 2048]
    const float* w2    = (const float*)d_in[2];   // [512, 512]
    const float* w3    = (const float*)d_in[3];   // [256, 512]
    const float* w_out = (const float*)d_in[4];   // [100, 256]
    const float* fs    = (const float*)d_in[5];
    const float* es    = (const float*)d_in[6];
    float* out = (float*)d_out;

    void *pC, *pA1, *pA2, *pA3, *pA4;
    cudaGetSymbolAddress(&pC,  g_C);
    cudaGetSymbolAddress(&pA1, g_A1);
    cudaGetSymbolAddress(&pA2, g_A2);
    cudaGetSymbolAddress(&pA3, g_A3);
    cudaGetSymbolAddress(&pA4, g_A4);
    float*    C  = (float*)pC;
    unsigned* A1 = (unsigned*)pA1;
    unsigned* A2 = (unsigned*)pA2;
    unsigned* A3 = (unsigned*)pA3;
    unsigned* A4 = (unsigned*)pA4;

    const int ROWBLKS = (TSTEPS / 4) * (BATCH / 32);   // 512

    // encoder -> A1 bits [t][wb][f]
    encoder_kernel<<<64 * 64, 256>>>(x, A1, fs);

    // layer 1: C = (5*es) * Z0 @ w1^T
    gemm_bits_kernel<<<dim3(4, ROWBLKS), 256>>>(A1, w1, C, 2048, 512, es, 5.0f);
    lif_scan_kernel<<<(512 * BATCH) / 256, 256>>>(C, A2, 512);

    // layer 2
    gemm_bits_kernel<<<dim3(4, ROWBLKS), 256>>>(A2, w2, C, 512, 512, nullptr, 1.0f);
    lif_scan_kernel<<<(512 * BATCH) / 256, 256>>>(C, A3, 512);

    // layer 3
    gemm_bits_kernel<<<dim3(2, ROWBLKS), 256>>>(A3, w3, C, 512, 256, nullptr, 1.0f);
    lif_scan_kernel<<<(256 * BATCH) / 256, 256>>>(C, A4, 256);

    // output layer (N=100, one 128-wide n-block with guards)
    gemm_bits_kernel<<<dim3(1, ROWBLKS), 256>>>(A4, w_out, C, 256, 100, nullptr, 1.0f);

    // LI decode
    decode_kernel<<<(100 * BATCH) / 256, 256>>>(C, out);
}